// round 1
// baseline (speedup 1.0000x reference)
#include <cuda_runtime.h>
#include <math.h>

#define D 128
#define NLIT 8000
#define NCLA 16000
#define TSTEPS 8
#define MAX_NNZ (1 << 20)

// ---------------- persistent scratch (device globals; no allocs) -------------
__device__ float g_LCpre[NLIT * D];
__device__ float g_Cmsg[NCLA * D];
__device__ float g_Cs[NCLA * D];
__device__ float g_hC[NCLA * D];
__device__ float g_CLpre[NCLA * D];
__device__ float g_Lmsg[NLIT * D];
__device__ float g_L[2][NLIT * D];
__device__ float g_hL[NLIT * D];
__device__ float g_inp[NLIT * 2 * D];
__device__ float g_gatesC[NCLA * 4 * D];
__device__ float g_gatesL[NLIT * 4 * D];

__device__ int g_nnz;
__device__ int g_pairs[MAX_NNZ];
__device__ int g_cntL[NLIT], g_cntC[NCLA];
__device__ int g_fillL[NLIT], g_fillC[NCLA];
__device__ int g_ptrL[NLIT + 1], g_ptrC[NCLA + 1];
__device__ int g_colL[MAX_NNZ];  // per-literal: clause indices
__device__ int g_colC[MAX_NNZ];  // per-clause: literal indices

// ---------------- small helpers ---------------------------------------------
__global__ void k_reset() {
    int i = blockIdx.x * blockDim.x + threadIdx.x;
    if (i < NLIT) { g_cntL[i] = 0; g_fillL[i] = 0; }
    if (i < NCLA) { g_cntC[i] = 0; g_fillC[i] = 0; }
    if (i == 0) g_nnz = 0;
}

__global__ void k_copy(float* __restrict__ dst, const float* __restrict__ src, int n) {
    int i = blockIdx.x * blockDim.x + threadIdx.x;
    int stride = gridDim.x * blockDim.x;
    for (; i < n; i += stride) dst[i] = src[i];
}

// Scan dense M once, record nnz pairs + per-row counts for both orientations.
__global__ void k_count(const float* __restrict__ M) {
    const int total4 = (NLIT * NCLA) / 4;  // 32M float4
    int stride = gridDim.x * blockDim.x;
    for (int i = blockIdx.x * blockDim.x + threadIdx.x; i < total4; i += stride) {
        float4 v = ((const float4*)M)[i];
        int base = i << 2;
        float vals[4] = {v.x, v.y, v.z, v.w};
        #pragma unroll
        for (int j = 0; j < 4; j++) {
            if (vals[j] != 0.0f) {
                int idx = base + j;
                int l = idx / NCLA;
                int c = idx - l * NCLA;
                int p = atomicAdd(&g_nnz, 1);
                if (p < MAX_NNZ) g_pairs[p] = idx;
                atomicAdd(&g_cntL[l], 1);
                atomicAdd(&g_cntC[c], 1);
            }
        }
    }
}

// single-block exclusive scan: ptr[0..n], ptr[n] = total
__global__ void k_scan(const int* __restrict__ cnt, int* __restrict__ ptr, int n) {
    __shared__ int sums[1024];
    int t = threadIdx.x;
    int chunk = (n + blockDim.x - 1) / blockDim.x;
    int start = t * chunk;
    int end = min(start + chunk, n);
    int s = 0;
    for (int i = start; i < end; i++) { ptr[i] = s; s += cnt[i]; }
    sums[t] = s;
    __syncthreads();
    for (int off = 1; off < 1024; off <<= 1) {
        int v = (t >= off) ? sums[t - off] : 0;
        __syncthreads();
        sums[t] += v;
        __syncthreads();
    }
    int base = (t == 0) ? 0 : sums[t - 1];
    for (int i = start; i < end; i++) ptr[i] += base;
    if (t == blockDim.x - 1) ptr[n] = sums[t];
}

__global__ void k_fill() {
    int nnz = g_nnz;
    if (nnz > MAX_NNZ) nnz = MAX_NNZ;
    int stride = gridDim.x * blockDim.x;
    for (int p = blockIdx.x * blockDim.x + threadIdx.x; p < nnz; p += stride) {
        int idx = g_pairs[p];
        int l = idx / NCLA;
        int c = idx - l * NCLA;
        int a = atomicAdd(&g_fillL[l], 1);
        g_colL[g_ptrL[l] + a] = c;
        int b = atomicAdd(&g_fillC[c], 1);
        g_colC[g_ptrC[c] + b] = l;
    }
}

// Y[r,:] = sum_{j in row r} X[col[j],:]   (128 threads = one D-vector)
__global__ void k_spmm(const int* __restrict__ ptr, const int* __restrict__ col,
                       const float* __restrict__ X, float* __restrict__ Y) {
    int r = blockIdx.x;
    int d = threadIdx.x;
    int beg = ptr[r], end = ptr[r + 1];
    float acc = 0.0f;
    int j = beg;
    for (; j + 3 < end; j += 4) {
        int c0 = col[j], c1 = col[j + 1], c2 = col[j + 2], c3 = col[j + 3];
        acc += X[c0 * D + d] + X[c1 * D + d] + X[c2 * D + d] + X[c3 * D + d];
    }
    for (; j < end; j++) acc += X[col[j] * D + d];
    Y[r * D + d] = acc;
}

// Y[M,N] = A1 @ W1^T (+ A2 @ W2^T) (+ b1 + b2). W row-major (N,K).
// BM=BN=64, BK=16, 256 threads, 4x4 per thread. All dims divisible.
__global__ void __launch_bounds__(256) k_gemm(
    const float* __restrict__ A1, const float* __restrict__ W1, int K1,
    const float* __restrict__ A2, const float* __restrict__ W2, int K2,
    const float* __restrict__ b1, const float* __restrict__ b2,
    float* __restrict__ Y, int N) {
    __shared__ float As[16][64];
    __shared__ float Bs[16][64];
    int m0 = blockIdx.y * 64, n0 = blockIdx.x * 64;
    int t = threadIdx.x;
    int lr = t >> 2;         // 0..63 (load row within tile)
    int lc = (t & 3) * 4;    // 0,4,8,12 (k offset)
    int tm = t >> 4;         // 0..15
    int tn = t & 15;         // 0..15
    float acc[4][4] = {};

    #pragma unroll
    for (int seg = 0; seg < 2; seg++) {
        const float* A = seg ? A2 : A1;
        const float* W = seg ? W2 : W1;
        int K = seg ? K2 : K1;
        if (!A) continue;
        for (int k0 = 0; k0 < K; k0 += 16) {
            float4 av = *(const float4*)(A + (size_t)(m0 + lr) * K + k0 + lc);
            float4 wv = *(const float4*)(W + (size_t)(n0 + lr) * K + k0 + lc);
            __syncthreads();
            As[lc + 0][lr] = av.x; As[lc + 1][lr] = av.y;
            As[lc + 2][lr] = av.z; As[lc + 3][lr] = av.w;
            Bs[lc + 0][lr] = wv.x; Bs[lc + 1][lr] = wv.y;
            Bs[lc + 2][lr] = wv.z; Bs[lc + 3][lr] = wv.w;
            __syncthreads();
            #pragma unroll
            for (int k = 0; k < 16; k++) {
                float4 a = *(const float4*)&As[k][tm * 4];
                float4 b = *(const float4*)&Bs[k][tn * 4];
                float av4[4] = {a.x, a.y, a.z, a.w};
                float bv4[4] = {b.x, b.y, b.z, b.w};
                #pragma unroll
                for (int i = 0; i < 4; i++)
                    #pragma unroll
                    for (int j = 0; j < 4; j++)
                        acc[i][j] = fmaf(av4[i], bv4[j], acc[i][j]);
            }
        }
    }

    #pragma unroll
    for (int j = 0; j < 4; j++) {
        int n = n0 + tn * 4 + j;
        float bias = 0.0f;
        if (b1) bias += b1[n];
        if (b2) bias += b2[n];
        #pragma unroll
        for (int i = 0; i < 4; i++)
            Y[(size_t)(m0 + tm * 4 + i) * N + n] = acc[i][j] + bias;
    }
}

__device__ __forceinline__ float sigm(float x) { return 1.0f / (1.0f + expf(-x)); }

// gate order (torch LSTM): i, f, g, o.  c and h share a single state buffer.
__global__ void k_lstm(const float* __restrict__ gates, const float* __restrict__ c_old,
                       float* __restrict__ h_out, float* __restrict__ c_out, int rows) {
    int i = blockIdx.x * blockDim.x + threadIdx.x;
    if (i >= rows * D) return;
    int r = i / D, d = i - r * D;
    const float* g = gates + (size_t)r * 4 * D;
    float gi = g[d], gf = g[D + d], gg = g[2 * D + d], go = g[3 * D + d];
    float c = c_old[i];
    float cn = sigm(gf) * c + sigm(gi) * tanhf(gg);
    float hn = sigm(go) * tanhf(cn);
    c_out[i] = cn;
    h_out[i] = hn;
}

// inp = [Lmsg | L]  (flip() in the reference is identity)
__global__ void k_concat(const float* __restrict__ Lmsg, const float* __restrict__ Lcur,
                         float* __restrict__ inp) {
    int i = blockIdx.x * blockDim.x + threadIdx.x;
    if (i >= NLIT * D) return;
    int r = i / D, d = i - r * D;
    inp[(size_t)r * 2 * D + d] = Lmsg[i];
    inp[(size_t)r * 2 * D + D + d] = Lcur[i];
}

// ---------------- host driver ------------------------------------------------
extern "C" void kernel_launch(void* const* d_in, const int* in_sizes, int n_in,
                              void* d_out, int out_size) {
    const float* L_state  = (const float*)d_in[0];
    const float* hidden_L = (const float*)d_in[2];
    const float* hidden_C = (const float*)d_in[3];
    const float* Mmat     = (const float*)d_in[4];
    int o = (n_in >= 18) ? 6 : 5;  // skip scalar n_vars if present
    const float* W_lc  = (const float*)d_in[o + 0];
    const float* b_lc  = (const float*)d_in[o + 1];
    const float* W_cl  = (const float*)d_in[o + 2];
    const float* b_cl  = (const float*)d_in[o + 3];
    const float* Wih_C = (const float*)d_in[o + 4];
    const float* Whh_C = (const float*)d_in[o + 5];
    const float* bih_C = (const float*)d_in[o + 6];
    const float* bhh_C = (const float*)d_in[o + 7];
    const float* Wih_L = (const float*)d_in[o + 8];
    const float* Whh_L = (const float*)d_in[o + 9];
    const float* bih_L = (const float*)d_in[o + 10];
    const float* bhh_L = (const float*)d_in[o + 11];

    void* p;
    cudaGetSymbolAddress(&p, g_L);      float* Lbuf   = (float*)p;
    cudaGetSymbolAddress(&p, g_hL);     float* hL     = (float*)p;
    cudaGetSymbolAddress(&p, g_hC);     float* hC     = (float*)p;
    cudaGetSymbolAddress(&p, g_LCpre);  float* LCpre  = (float*)p;
    cudaGetSymbolAddress(&p, g_Cmsg);   float* Cmsg   = (float*)p;
    cudaGetSymbolAddress(&p, g_Cs);     float* Cs     = (float*)p;
    cudaGetSymbolAddress(&p, g_CLpre);  float* CLpre  = (float*)p;
    cudaGetSymbolAddress(&p, g_Lmsg);   float* Lmsg   = (float*)p;
    cudaGetSymbolAddress(&p, g_inp);    float* inp    = (float*)p;
    cudaGetSymbolAddress(&p, g_gatesC); float* gatesC = (float*)p;
    cudaGetSymbolAddress(&p, g_gatesL); float* gatesL = (float*)p;
    cudaGetSymbolAddress(&p, g_ptrL);   int* ptrL = (int*)p;
    cudaGetSymbolAddress(&p, g_ptrC);   int* ptrC = (int*)p;
    cudaGetSymbolAddress(&p, g_colL);   int* colL = (int*)p;
    cudaGetSymbolAddress(&p, g_colC);   int* colC = (int*)p;
    cudaGetSymbolAddress(&p, g_cntL);   int* cntL = (int*)p;
    cudaGetSymbolAddress(&p, g_cntC);   int* cntC = (int*)p;

    // ---- CSR build (must be redone every launch; no caching allowed) ----
    k_reset<<<(NCLA + 255) / 256, 256>>>();
    k_count<<<2048, 256>>>(Mmat);
    k_scan<<<1, 1024>>>(cntL, ptrL, NLIT);
    k_scan<<<1, 1024>>>(cntC, ptrC, NCLA);
    k_fill<<<512, 256>>>();

    // ---- state init ----
    cudaMemcpyAsync(Lbuf, L_state, sizeof(float) * NLIT * D, cudaMemcpyDeviceToDevice);
    cudaMemcpyAsync(hC, hidden_C, sizeof(float) * NCLA * D, cudaMemcpyDeviceToDevice);
    cudaMemcpyAsync(hL, hidden_L, sizeof(float) * NLIT * D, cudaMemcpyDeviceToDevice);

    // ---- T message-passing rounds ----
    for (int r = 0; r < TSTEPS; r++) {
        float* Lcur  = Lbuf + (size_t)(r & 1) * NLIT * D;
        float* Lnext = Lbuf + (size_t)((r + 1) & 1) * NLIT * D;

        // LC_pre = L @ W_lc^T + b_lc
        k_gemm<<<dim3(D / 64, NLIT / 64), 256>>>(Lcur, W_lc, D, nullptr, nullptr, 0,
                                                 b_lc, nullptr, LCpre, D);
        // LC_msgs = M^T @ LC_pre
        k_spmm<<<NCLA, 128>>>(ptrC, colC, LCpre, Cmsg);
        // C gates = Cmsg @ Wih_C^T + hC @ Whh_C^T + bih + bhh
        k_gemm<<<dim3(4 * D / 64, NCLA / 64), 256>>>(Cmsg, Wih_C, D, hC, Whh_C, D,
                                                     bih_C, bhh_C, gatesC, 4 * D);
        k_lstm<<<(NCLA * D + 255) / 256, 256>>>(gatesC, hC, Cs, hC, NCLA);
        // CL_pre = Cs @ W_cl^T + b_cl
        k_gemm<<<dim3(D / 64, NCLA / 64), 256>>>(Cs, W_cl, D, nullptr, nullptr, 0,
                                                 b_cl, nullptr, CLpre, D);
        // CL_msgs = M @ CL_pre
        k_spmm<<<NLIT, 128>>>(ptrL, colL, CLpre, Lmsg);
        // inp = [CL_msgs | L]
        k_concat<<<(NLIT * D + 255) / 256, 256>>>(Lmsg, Lcur, inp);
        // L gates = inp @ Wih_L^T + hL @ Whh_L^T + biases
        k_gemm<<<dim3(4 * D / 64, NLIT / 64), 256>>>(inp, Wih_L, 2 * D, hL, Whh_L, D,
                                                     bih_L, bhh_L, gatesL, 4 * D);
        k_lstm<<<(NLIT * D + 255) / 256, 256>>>(gatesL, hL, Lnext, hL, NLIT);
    }

    // after 8 rounds the latest L lives in buffer 0
    cudaMemcpyAsync(d_out, Lbuf, sizeof(float) * NLIT * D, cudaMemcpyDeviceToDevice);
}